// round 8
// baseline (speedup 1.0000x reference)
#include <cuda_runtime.h>
#include <cuda_bf16.h>
#include <math.h>
#include <stdint.h>

// ---------------------------------------------------------------------------
// PredictorLG fused MLP:  LN -> (GEMM+GELU)x3 -> GEMM(->2) -> log_softmax
// R7: L1-traffic diet. CHUNK=192 (NF=6) for layers 1-2 cuts A ldmatrix
// redundancy 12->8 (L1) and 8->4 (L2). 2-slot B prefetch to fit 128 regs.
// ---------------------------------------------------------------------------

#define ROWS_TILE   64
#define NTHREADS    256
#define LD          392           // padded activation row stride (halfs)
#define RTOT        262144
#define ROWS_PER_M  131072

#define S1 (384*384)
#define S2 (384*192)
#define S3 (192*96)
#define MOD_STRIDE (S1+S2+S3)
#define OFF_L2 (S1)
#define OFF_L3 (S1+S2)

__device__ __align__(16) __nv_bfloat16 g_packedW[2 * MOD_STRIDE];

// ---------------------------------------------------------------------------
// Weight repack: W[k][n] fp32 -> pair-kt B-fragment layout (16B/lane covers
// two consecutive kt):
//   dst = base + ((nt*KTP + ktp)*32 + lane)*8 + (kt&1)*4 + reg*2 + i
//   lane = (n%8)*4 + ((k%8)>>1);  reg = (k>>3)&1;  i = k&1
// ---------------------------------------------------------------------------
__global__ void pack_weights_kernel(const float* __restrict__ W1,
                                    const float* __restrict__ W2,
                                    const float* __restrict__ W3) {
    int idx = blockIdx.x * blockDim.x + threadIdx.x;
    const float* src;
    int K, N, r, m, layerOff;
    if (idx < 2 * S1) {
        m = idx / S1; r = idx % S1; K = 384; N = 384;
        src = W1 + m * S1; layerOff = 0;
    } else if (idx < 2 * (S1 + S2)) {
        int e = idx - 2 * S1;
        m = e / S2; r = e % S2; K = 384; N = 192;
        src = W2 + m * S2; layerOff = OFF_L2;
    } else if (idx < 2 * (S1 + S2 + S3)) {
        int e = idx - 2 * (S1 + S2);
        m = e / S3; r = e % S3; K = 192; N = 96;
        src = W3 + m * S3; layerOff = OFF_L3;
    } else {
        return;
    }
    int k = r / N, n = r % N;
    int kt  = k >> 4;
    int ktp = kt >> 1;
    int KTP = K >> 5;
    int nt  = n >> 3;
    int lane = (n & 7) * 4 + ((k & 7) >> 1);
    int reg  = (k >> 3) & 1;
    int i    = k & 1;
    int dst  = m * MOD_STRIDE + layerOff +
               ((nt * KTP + ktp) * 32 + lane) * 8 + (kt & 1) * 4 + reg * 2 + i;
    g_packedW[dst] = __float2bfloat16(src[k * N + n]);
}

// ---------------------------------------------------------------------------
// mma / ldmatrix / gelu helpers
// ---------------------------------------------------------------------------
__device__ __forceinline__ void mma16816(float c[4], const unsigned a[4],
                                         const unsigned b0, const unsigned b1) {
    asm volatile(
        "mma.sync.aligned.m16n8k16.row.col.f32.bf16.bf16.f32 "
        "{%0,%1,%2,%3}, {%4,%5,%6,%7}, {%8,%9}, {%0,%1,%2,%3};\n"
        : "+f"(c[0]), "+f"(c[1]), "+f"(c[2]), "+f"(c[3])
        : "r"(a[0]), "r"(a[1]), "r"(a[2]), "r"(a[3]), "r"(b0), "r"(b1));
}

__device__ __forceinline__ void ldmatrix_x4(unsigned r[4], uint32_t addr) {
    asm volatile(
        "ldmatrix.sync.aligned.m8n8.x4.shared.b16 {%0,%1,%2,%3}, [%4];\n"
        : "=r"(r[0]), "=r"(r[1]), "=r"(r[2]), "=r"(r[3])
        : "r"(addr));
}

// fast GELU: tanh approximation with HW MUFU.TANH
__device__ __forceinline__ float gelu_fast(float v) {
    float u = v * (0.7978845608028654f + 0.0447149985f * v * v);
    float t;
    asm("tanh.approx.f32 %0, %1;" : "=f"(t) : "f"(u));
    float h = 0.5f * v;
    return h + h * t;
}

// ---------------------------------------------------------------------------
// One GEMM layer: out = gelu(in[64,K] @ W[K,N] + bias).
// Warp grid 2(m) x 4(n); B as uint4 (two kt per load), 2-slot circular
// prefetch (1 pair = 2 kt ahead), static indices under full unroll.
// ---------------------------------------------------------------------------
template <int K, int N, int CHUNK>
__device__ __forceinline__ void gemm_layer(const __nv_bfloat16* inBuf,
                                           __nv_bfloat16* outBuf,
                                           const __nv_bfloat16* __restrict__ Wp,
                                           const float* __restrict__ s_bias) {
    constexpr int NPASS = N / CHUNK;
    constexpr int CW  = CHUNK / 4;
    constexpr int NF  = CW / 8;
    constexpr int KT  = K / 16;
    constexpr int KTP = KT / 2;

    const int tid  = threadIdx.x;
    const int lane = tid & 31;
    const int wid  = tid >> 5;
    const int wm   = wid & 1;
    const int wn   = wid >> 1;

    uint32_t sA = (uint32_t)__cvta_generic_to_shared(inBuf);
    const int arow     = wm * 32 + (lane & 15);
    const int acol_off = (lane >> 4) * 8;
    const uint32_t aBase = sA + (uint32_t)((arow * LD + acol_off) * 2);

    const uint4* bb = (const uint4*)Wp;

#pragma unroll
    for (int p = 0; p < NPASS; ++p) {
        float acc[2][NF][4];
#pragma unroll
        for (int mi = 0; mi < 2; ++mi)
#pragma unroll
            for (int nf = 0; nf < NF; ++nf)
#pragma unroll
                for (int q = 0; q < 4; ++q) acc[mi][nf][q] = 0.f;

        const int colbase = p * CHUNK + wn * CW;
        const int ntbase  = colbase >> 3;
        const uint4* bwarp = bb + (size_t)ntbase * KTP * 32 + lane;

        // 2-slot circular prefetch buffer, static indices (full unroll)
        uint4 bf[2][NF];
#pragma unroll
        for (int nf = 0; nf < NF; ++nf)
            bf[0][nf] = __ldg(bwarp + (size_t)nf * KTP * 32);

#pragma unroll
        for (int ktp = 0; ktp < KTP; ++ktp) {
            const int cur = ktp & 1;
            const int nxt = cur ^ 1;
            if (ktp + 1 < KTP) {
#pragma unroll
                for (int nf = 0; nf < NF; ++nf)
                    bf[nxt][nf] = __ldg(bwarp + (size_t)nf * KTP * 32 + (ktp + 1) * 32);
            }
            // kt even
            {
                unsigned a[2][4];
                uint32_t addr0 = aBase + (uint32_t)((2 * ktp) * 32);
                ldmatrix_x4(a[0], addr0);
                ldmatrix_x4(a[1], addr0 + 16 * LD * 2);
#pragma unroll
                for (int nf = 0; nf < NF; ++nf) {
                    mma16816(acc[0][nf], a[0], bf[cur][nf].x, bf[cur][nf].y);
                    mma16816(acc[1][nf], a[1], bf[cur][nf].x, bf[cur][nf].y);
                }
            }
            // kt odd
            {
                unsigned a[2][4];
                uint32_t addr0 = aBase + (uint32_t)((2 * ktp + 1) * 32);
                ldmatrix_x4(a[0], addr0);
                ldmatrix_x4(a[1], addr0 + 16 * LD * 2);
#pragma unroll
                for (int nf = 0; nf < NF; ++nf) {
                    mma16816(acc[0][nf], a[0], bf[cur][nf].z, bf[cur][nf].w);
                    mma16816(acc[1][nf], a[1], bf[cur][nf].z, bf[cur][nf].w);
                }
            }
        }

        // epilogue: bias + fast gelu + bf16 store
        const int r0 = wm * 32 + (lane >> 2);
        const int cb = colbase + (lane & 3) * 2;
#pragma unroll
        for (int nf = 0; nf < NF; ++nf) {
            const int c = cb + nf * 8;
            const float bi0 = s_bias[c];
            const float bi1 = s_bias[c + 1];
#pragma unroll
            for (int mi = 0; mi < 2; ++mi) {
                const int row = r0 + mi * 16;
                float v0 = gelu_fast(acc[mi][nf][0] + bi0);
                float v1 = gelu_fast(acc[mi][nf][1] + bi1);
                float v2 = gelu_fast(acc[mi][nf][2] + bi0);
                float v3 = gelu_fast(acc[mi][nf][3] + bi1);
                *(__nv_bfloat162*)(outBuf + row * LD + c) =
                    __floats2bfloat162_rn(v0, v1);
                *(__nv_bfloat162*)(outBuf + (row + 8) * LD + c) =
                    __floats2bfloat162_rn(v2, v3);
            }
        }
    }
}

// ---------------------------------------------------------------------------
// Fused kernel
// ---------------------------------------------------------------------------
__global__ void __launch_bounds__(NTHREADS, 2)
fused_mlp_kernel(const float* __restrict__ x,
                 const float* __restrict__ ln_g,
                 const float* __restrict__ ln_b,
                 const float* __restrict__ b1,
                 const float* __restrict__ b2,
                 const float* __restrict__ b3,
                 const float* __restrict__ W4,
                 const float* __restrict__ b4,
                 float* __restrict__ out) {
    extern __shared__ __align__(16) char smem_raw[];
    __nv_bfloat16* bufA = (__nv_bfloat16*)smem_raw;                 // [64][392]
    __nv_bfloat16* bufB = bufA + ROWS_TILE * LD;                    // [64][392]
    float* s_bias = (float*)(bufB + ROWS_TILE * LD);                // [384]

    const int tid  = threadIdx.x;
    const int lane = tid & 31;
    const int wid  = tid >> 5;
    const long row0 = (long)blockIdx.x * ROWS_TILE;
    const int m = (int)(row0 / ROWS_PER_M);

    // ------------------- Stage 0: LayerNorm -> bufA (bf16) -----------------
    {
        float4 g4[3], bb4[3];
#pragma unroll
        for (int j = 0; j < 3; ++j) {
            g4[j]  = ((const float4*)(ln_g + m * 384))[j * 32 + lane];
            bb4[j] = ((const float4*)(ln_b + m * 384))[j * 32 + lane];
        }
#pragma unroll
        for (int r = wid; r < ROWS_TILE; r += 8) {
            const float4* xr = (const float4*)(x + (row0 + r) * 384);
            float4 v[3];
            float s = 0.f, q = 0.f;
#pragma unroll
            for (int j = 0; j < 3; ++j) {
                v[j] = xr[j * 32 + lane];
                s += v[j].x + v[j].y + v[j].z + v[j].w;
                q += v[j].x * v[j].x + v[j].y * v[j].y +
                     v[j].z * v[j].z + v[j].w * v[j].w;
            }
#pragma unroll
            for (int off = 16; off; off >>= 1) {
                s += __shfl_xor_sync(0xffffffffu, s, off);
                q += __shfl_xor_sync(0xffffffffu, q, off);
            }
            const float mu   = s * (1.0f / 384.0f);
            const float var  = q * (1.0f / 384.0f) - mu * mu;
            const float rinv = rsqrtf(var + 1e-5f);
#pragma unroll
            for (int j = 0; j < 3; ++j) {
                const int c = (j * 32 + lane) * 4;
                float y0 = (v[j].x - mu) * rinv * g4[j].x + bb4[j].x;
                float y1 = (v[j].y - mu) * rinv * g4[j].y + bb4[j].y;
                float y2 = (v[j].z - mu) * rinv * g4[j].z + bb4[j].z;
                float y3 = (v[j].w - mu) * rinv * g4[j].w + bb4[j].w;
                *(__nv_bfloat162*)(bufA + r * LD + c)     = __floats2bfloat162_rn(y0, y1);
                *(__nv_bfloat162*)(bufA + r * LD + c + 2) = __floats2bfloat162_rn(y2, y3);
            }
        }
    }

    const __nv_bfloat16* WpBase = g_packedW + (size_t)m * MOD_STRIDE;

    // ------------------- Layer 1: 384 -> 384 (2 passes of 192) -------------
    __syncthreads();
    for (int i = tid; i < 384; i += NTHREADS) s_bias[i] = b1[m * 384 + i];
    __syncthreads();
    gemm_layer<384, 384, 192>(bufA, bufB, WpBase, s_bias);

    // ------------------- Layer 2: 384 -> 192 (1 pass of 192) ---------------
    __syncthreads();
    if (tid < 192) s_bias[tid] = b2[m * 192 + tid];
    __syncthreads();
    gemm_layer<384, 192, 192>(bufB, bufA, WpBase + OFF_L2, s_bias);

    // ------------------- Layer 3: 192 -> 96 (1 pass of 96) -----------------
    __syncthreads();
    if (tid < 96) s_bias[tid] = b3[m * 96 + tid];
    __syncthreads();
    gemm_layer<192, 96, 96>(bufA, bufB, WpBase + OFF_L3, s_bias);

    // ------------------- Layer 4: 96 -> 2 + log_softmax --------------------
    __syncthreads();
    {
        const int r    = tid >> 2;
        const int part = tid & 3;
        const float* w4 = W4 + m * 96 * 2;
        const __nv_bfloat16* hrow = bufB + r * LD;
        float z0 = 0.f, z1 = 0.f;
#pragma unroll
        for (int kk = 0; kk < 24; ++kk) {
            const int k = part * 24 + kk;
            float a = __bfloat162float(hrow[k]);
            z0 += a * w4[k * 2 + 0];
            z1 += a * w4[k * 2 + 1];
        }
        z0 += __shfl_xor_sync(0xffffffffu, z0, 1);
        z0 += __shfl_xor_sync(0xffffffffu, z0, 2);
        z1 += __shfl_xor_sync(0xffffffffu, z1, 1);
        z1 += __shfl_xor_sync(0xffffffffu, z1, 2);
        if (part == 0) {
            z0 += b4[m * 2 + 0];
            z1 += b4[m * 2 + 1];
            const float mx  = fmaxf(z0, z1);
            const float lse = mx + logf(expf(z0 - mx) + expf(z1 - mx));
            float* o = out + (row0 + r) * 2;
            o[0] = z0 - lse;
            o[1] = z1 - lse;
        }
    }
}

// ---------------------------------------------------------------------------
// Launch
// ---------------------------------------------------------------------------
extern "C" void kernel_launch(void* const* d_in, const int* in_sizes, int n_in,
                              void* d_out, int out_size) {
    const float* x    = (const float*)d_in[0];
    const float* ln_g = (const float*)d_in[1];
    const float* ln_b = (const float*)d_in[2];
    const float* W1   = (const float*)d_in[3];
    const float* b1   = (const float*)d_in[4];
    const float* W2   = (const float*)d_in[5];
    const float* b2   = (const float*)d_in[6];
    const float* W3   = (const float*)d_in[7];
    const float* b3   = (const float*)d_in[8];
    const float* W4   = (const float*)d_in[9];
    const float* b4   = (const float*)d_in[10];
    float* out        = (float*)d_out;

    const int packTotal = 2 * MOD_STRIDE;
    pack_weights_kernel<<<(packTotal + 255) / 256, 256>>>(W1, W2, W3);

    const int smem_bytes = 2 * ROWS_TILE * LD * (int)sizeof(__nv_bfloat16)
                         + 384 * (int)sizeof(float);
    cudaFuncSetAttribute(fused_mlp_kernel,
                         cudaFuncAttributeMaxDynamicSharedMemorySize, smem_bytes);
    fused_mlp_kernel<<<RTOT / ROWS_TILE, NTHREADS, smem_bytes>>>(
        x, ln_g, ln_b, b1, b2, b3, W4, b4, out);
}

// round 9
// speedup vs baseline: 1.0288x; 1.0288x over previous
#include <cuda_runtime.h>
#include <cuda_bf16.h>
#include <math.h>
#include <stdint.h>

// ---------------------------------------------------------------------------
// PredictorLG fused MLP:  LN -> (GEMM+GELU)x3 -> GEMM(->2) -> log_softmax
// R9: R6 tile config (CHUNK 128/96/96) + A-fragment double buffering so
// LDSM latency overlaps the HMMA chain. B: pair-kt uint4, 2-slot prefetch.
// ---------------------------------------------------------------------------

#define ROWS_TILE   64
#define NTHREADS    256
#define LD          392           // padded activation row stride (halfs)
#define RTOT        262144
#define ROWS_PER_M  131072

#define S1 (384*384)
#define S2 (384*192)
#define S3 (192*96)
#define MOD_STRIDE (S1+S2+S3)
#define OFF_L2 (S1)
#define OFF_L3 (S1+S2)

__device__ __align__(16) __nv_bfloat16 g_packedW[2 * MOD_STRIDE];

// ---------------------------------------------------------------------------
// Weight repack: W[k][n] fp32 -> pair-kt B-fragment layout (16B/lane covers
// two consecutive kt):
//   dst = base + ((nt*KTP + ktp)*32 + lane)*8 + (kt&1)*4 + reg*2 + i
//   lane = (n%8)*4 + ((k%8)>>1);  reg = (k>>3)&1;  i = k&1
// ---------------------------------------------------------------------------
__global__ void pack_weights_kernel(const float* __restrict__ W1,
                                    const float* __restrict__ W2,
                                    const float* __restrict__ W3) {
    int idx = blockIdx.x * blockDim.x + threadIdx.x;
    const float* src;
    int K, N, r, m, layerOff;
    if (idx < 2 * S1) {
        m = idx / S1; r = idx % S1; K = 384; N = 384;
        src = W1 + m * S1; layerOff = 0;
    } else if (idx < 2 * (S1 + S2)) {
        int e = idx - 2 * S1;
        m = e / S2; r = e % S2; K = 384; N = 192;
        src = W2 + m * S2; layerOff = OFF_L2;
    } else if (idx < 2 * (S1 + S2 + S3)) {
        int e = idx - 2 * (S1 + S2);
        m = e / S3; r = e % S3; K = 192; N = 96;
        src = W3 + m * S3; layerOff = OFF_L3;
    } else {
        return;
    }
    int k = r / N, n = r % N;
    int kt  = k >> 4;
    int ktp = kt >> 1;
    int KTP = K >> 5;
    int nt  = n >> 3;
    int lane = (n & 7) * 4 + ((k & 7) >> 1);
    int reg  = (k >> 3) & 1;
    int i    = k & 1;
    int dst  = m * MOD_STRIDE + layerOff +
               ((nt * KTP + ktp) * 32 + lane) * 8 + (kt & 1) * 4 + reg * 2 + i;
    g_packedW[dst] = __float2bfloat16(src[k * N + n]);
}

// ---------------------------------------------------------------------------
// mma / ldmatrix / gelu helpers
// ---------------------------------------------------------------------------
__device__ __forceinline__ void mma16816(float c[4], const unsigned a[4],
                                         const unsigned b0, const unsigned b1) {
    asm volatile(
        "mma.sync.aligned.m16n8k16.row.col.f32.bf16.bf16.f32 "
        "{%0,%1,%2,%3}, {%4,%5,%6,%7}, {%8,%9}, {%0,%1,%2,%3};\n"
        : "+f"(c[0]), "+f"(c[1]), "+f"(c[2]), "+f"(c[3])
        : "r"(a[0]), "r"(a[1]), "r"(a[2]), "r"(a[3]), "r"(b0), "r"(b1));
}

__device__ __forceinline__ void ldmatrix_x4(unsigned r[4], uint32_t addr) {
    asm volatile(
        "ldmatrix.sync.aligned.m8n8.x4.shared.b16 {%0,%1,%2,%3}, [%4];\n"
        : "=r"(r[0]), "=r"(r[1]), "=r"(r[2]), "=r"(r[3])
        : "r"(addr));
}

// fast GELU: tanh approximation with HW MUFU.TANH
__device__ __forceinline__ float gelu_fast(float v) {
    float u = v * (0.7978845608028654f + 0.0447149985f * v * v);
    float t;
    asm("tanh.approx.f32 %0, %1;" : "=f"(t) : "f"(u));
    float h = 0.5f * v;
    return h + h * t;
}

// ---------------------------------------------------------------------------
// One GEMM layer: out = gelu(in[64,K] @ W[K,N] + bias).
// Warp grid 2(m) x 4(n). A fragments double-buffered (prefetch kt+1 during
// kt's MMAs); B as uint4 pair-kt loads, 2-slot prefetch.
// ---------------------------------------------------------------------------
template <int K, int N, int CHUNK>
__device__ __forceinline__ void gemm_layer(const __nv_bfloat16* inBuf,
                                           __nv_bfloat16* outBuf,
                                           const __nv_bfloat16* __restrict__ Wp,
                                           const float* __restrict__ s_bias) {
    constexpr int NPASS = N / CHUNK;
    constexpr int CW  = CHUNK / 4;
    constexpr int NF  = CW / 8;
    constexpr int KT  = K / 16;
    constexpr int KTP = KT / 2;

    const int tid  = threadIdx.x;
    const int lane = tid & 31;
    const int wid  = tid >> 5;
    const int wm   = wid & 1;
    const int wn   = wid >> 1;

    uint32_t sA = (uint32_t)__cvta_generic_to_shared(inBuf);
    const int arow     = wm * 32 + (lane & 15);
    const int acol_off = (lane >> 4) * 8;
    const uint32_t aBase = sA + (uint32_t)((arow * LD + acol_off) * 2);

    const uint4* bb = (const uint4*)Wp;

#pragma unroll
    for (int p = 0; p < NPASS; ++p) {
        float acc[2][NF][4];
#pragma unroll
        for (int mi = 0; mi < 2; ++mi)
#pragma unroll
            for (int nf = 0; nf < NF; ++nf)
#pragma unroll
                for (int q = 0; q < 4; ++q) acc[mi][nf][q] = 0.f;

        const int colbase = p * CHUNK + wn * CW;
        const int ntbase  = colbase >> 3;
        const uint4* bwarp = bb + (size_t)ntbase * KTP * 32 + lane;

        // B: 2-slot circular pair prefetch
        uint4 bf[2][NF];
#pragma unroll
        for (int nf = 0; nf < NF; ++nf)
            bf[0][nf] = __ldg(bwarp + (size_t)nf * KTP * 32);

        // A: double-buffered fragments
        unsigned a[2][2][4];
        ldmatrix_x4(a[0][0], aBase);
        ldmatrix_x4(a[0][1], aBase + 16 * LD * 2);

#pragma unroll
        for (int kt = 0; kt < KT; ++kt) {
            const int ktp  = kt >> 1;
            const int acur = kt & 1;
            const int anxt = acur ^ 1;
            const int bcur = ktp & 1;

            // prefetch next B pair at the start of each even kt
            if ((kt & 1) == 0 && ktp + 1 < KTP) {
#pragma unroll
                for (int nf = 0; nf < NF; ++nf)
                    bf[bcur ^ 1][nf] =
                        __ldg(bwarp + (size_t)nf * KTP * 32 + (ktp + 1) * 32);
            }
            // prefetch next A fragments (overlaps current MMAs)
            if (kt + 1 < KT) {
                uint32_t addr1 = aBase + (uint32_t)((kt + 1) * 32);
                ldmatrix_x4(a[anxt][0], addr1);
                ldmatrix_x4(a[anxt][1], addr1 + 16 * LD * 2);
            }

            const unsigned bx = (kt & 1) ? bf[bcur][0].z : bf[bcur][0].x; // placeholder avoided below
            (void)bx;
#pragma unroll
            for (int nf = 0; nf < NF; ++nf) {
                const unsigned w0 = (kt & 1) ? bf[bcur][nf].z : bf[bcur][nf].x;
                const unsigned w1 = (kt & 1) ? bf[bcur][nf].w : bf[bcur][nf].y;
                mma16816(acc[0][nf], a[acur][0], w0, w1);
                mma16816(acc[1][nf], a[acur][1], w0, w1);
            }
        }

        // epilogue: bias + fast gelu + bf16 store
        const int r0 = wm * 32 + (lane >> 2);
        const int cb = colbase + (lane & 3) * 2;
#pragma unroll
        for (int nf = 0; nf < NF; ++nf) {
            const int c = cb + nf * 8;
            const float bi0 = s_bias[c];
            const float bi1 = s_bias[c + 1];
#pragma unroll
            for (int mi = 0; mi < 2; ++mi) {
                const int row = r0 + mi * 16;
                float v0 = gelu_fast(acc[mi][nf][0] + bi0);
                float v1 = gelu_fast(acc[mi][nf][1] + bi1);
                float v2 = gelu_fast(acc[mi][nf][2] + bi0);
                float v3 = gelu_fast(acc[mi][nf][3] + bi1);
                *(__nv_bfloat162*)(outBuf + row * LD + c) =
                    __floats2bfloat162_rn(v0, v1);
                *(__nv_bfloat162*)(outBuf + (row + 8) * LD + c) =
                    __floats2bfloat162_rn(v2, v3);
            }
        }
    }
}

// ---------------------------------------------------------------------------
// Fused kernel
// ---------------------------------------------------------------------------
__global__ void __launch_bounds__(NTHREADS, 2)
fused_mlp_kernel(const float* __restrict__ x,
                 const float* __restrict__ ln_g,
                 const float* __restrict__ ln_b,
                 const float* __restrict__ b1,
                 const float* __restrict__ b2,
                 const float* __restrict__ b3,
                 const float* __restrict__ W4,
                 const float* __restrict__ b4,
                 float* __restrict__ out) {
    extern __shared__ __align__(16) char smem_raw[];
    __nv_bfloat16* bufA = (__nv_bfloat16*)smem_raw;                 // [64][392]
    __nv_bfloat16* bufB = bufA + ROWS_TILE * LD;                    // [64][392]
    float* s_bias = (float*)(bufB + ROWS_TILE * LD);                // [384]

    const int tid  = threadIdx.x;
    const int lane = tid & 31;
    const int wid  = tid >> 5;
    const long row0 = (long)blockIdx.x * ROWS_TILE;
    const int m = (int)(row0 / ROWS_PER_M);

    // ------------------- Stage 0: LayerNorm -> bufA (bf16) -----------------
    {
        float4 g4[3], bb4[3];
#pragma unroll
        for (int j = 0; j < 3; ++j) {
            g4[j]  = ((const float4*)(ln_g + m * 384))[j * 32 + lane];
            bb4[j] = ((const float4*)(ln_b + m * 384))[j * 32 + lane];
        }
#pragma unroll
        for (int r = wid; r < ROWS_TILE; r += 8) {
            const float4* xr = (const float4*)(x + (row0 + r) * 384);
            float4 v[3];
            float s = 0.f, q = 0.f;
#pragma unroll
            for (int j = 0; j < 3; ++j) {
                v[j] = xr[j * 32 + lane];
                s += v[j].x + v[j].y + v[j].z + v[j].w;
                q += v[j].x * v[j].x + v[j].y * v[j].y +
                     v[j].z * v[j].z + v[j].w * v[j].w;
            }
#pragma unroll
            for (int off = 16; off; off >>= 1) {
                s += __shfl_xor_sync(0xffffffffu, s, off);
                q += __shfl_xor_sync(0xffffffffu, q, off);
            }
            const float mu   = s * (1.0f / 384.0f);
            const float var  = q * (1.0f / 384.0f) - mu * mu;
            const float rinv = rsqrtf(var + 1e-5f);
#pragma unroll
            for (int j = 0; j < 3; ++j) {
                const int c = (j * 32 + lane) * 4;
                float y0 = (v[j].x - mu) * rinv * g4[j].x + bb4[j].x;
                float y1 = (v[j].y - mu) * rinv * g4[j].y + bb4[j].y;
                float y2 = (v[j].z - mu) * rinv * g4[j].z + bb4[j].z;
                float y3 = (v[j].w - mu) * rinv * g4[j].w + bb4[j].w;
                *(__nv_bfloat162*)(bufA + r * LD + c)     = __floats2bfloat162_rn(y0, y1);
                *(__nv_bfloat162*)(bufA + r * LD + c + 2) = __floats2bfloat162_rn(y2, y3);
            }
        }
    }

    const __nv_bfloat16* WpBase = g_packedW + (size_t)m * MOD_STRIDE;

    // ------------------- Layer 1: 384 -> 384 (3 passes of 128) -------------
    __syncthreads();
    for (int i = tid; i < 384; i += NTHREADS) s_bias[i] = b1[m * 384 + i];
    __syncthreads();
    gemm_layer<384, 384, 128>(bufA, bufB, WpBase, s_bias);

    // ------------------- Layer 2: 384 -> 192 (2 passes of 96) --------------
    __syncthreads();
    if (tid < 192) s_bias[tid] = b2[m * 192 + tid];
    __syncthreads();
    gemm_layer<384, 192, 96>(bufB, bufA, WpBase + OFF_L2, s_bias);

    // ------------------- Layer 3: 192 -> 96 (1 pass of 96) -----------------
    __syncthreads();
    if (tid < 96) s_bias[tid] = b3[m * 96 + tid];
    __syncthreads();
    gemm_layer<192, 96, 96>(bufA, bufB, WpBase + OFF_L3, s_bias);

    // ------------------- Layer 4: 96 -> 2 + log_softmax --------------------
    __syncthreads();
    {
        const int r    = tid >> 2;
        const int part = tid & 3;
        const float* w4 = W4 + m * 96 * 2;
        const __nv_bfloat16* hrow = bufB + r * LD;
        float z0 = 0.f, z1 = 0.f;
#pragma unroll
        for (int kk = 0; kk < 24; ++kk) {
            const int k = part * 24 + kk;
            float a = __bfloat162float(hrow[k]);
            z0 += a * w4[k * 2 + 0];
            z1 += a * w4[k * 2 + 1];
        }
        z0 += __shfl_xor_sync(0xffffffffu, z0, 1);
        z0 += __shfl_xor_sync(0xffffffffu, z0, 2);
        z1 += __shfl_xor_sync(0xffffffffu, z1, 1);
        z1 += __shfl_xor_sync(0xffffffffu, z1, 2);
        if (part == 0) {
            z0 += b4[m * 2 + 0];
            z1 += b4[m * 2 + 1];
            const float mx  = fmaxf(z0, z1);
            const float lse = mx + logf(expf(z0 - mx) + expf(z1 - mx));
            float* o = out + (row0 + r) * 2;
            o[0] = z0 - lse;
            o[1] = z1 - lse;
        }
    }
}

// ---------------------------------------------------------------------------
// Launch
// ---------------------------------------------------------------------------
extern "C" void kernel_launch(void* const* d_in, const int* in_sizes, int n_in,
                              void* d_out, int out_size) {
    const float* x    = (const float*)d_in[0];
    const float* ln_g = (const float*)d_in[1];
    const float* ln_b = (const float*)d_in[2];
    const float* W1   = (const float*)d_in[3];
    const float* b1   = (const float*)d_in[4];
    const float* W2   = (const float*)d_in[5];
    const float* b2   = (const float*)d_in[6];
    const float* W3   = (const float*)d_in[7];
    const float* b3   = (const float*)d_in[8];
    const float* W4   = (const float*)d_in[9];
    const float* b4   = (const float*)d_in[10];
    float* out        = (float*)d_out;

    const int packTotal = 2 * MOD_STRIDE;
    pack_weights_kernel<<<(packTotal + 255) / 256, 256>>>(W1, W2, W3);

    const int smem_bytes = 2 * ROWS_TILE * LD * (int)sizeof(__nv_bfloat16)
                         + 384 * (int)sizeof(float);
    cudaFuncSetAttribute(fused_mlp_kernel,
                         cudaFuncAttributeMaxDynamicSharedMemorySize, smem_bytes);
    fused_mlp_kernel<<<RTOT / ROWS_TILE, NTHREADS, smem_bytes>>>(
        x, ln_g, ln_b, b1, b2, b3, W4, b4, out);
}

// round 10
// speedup vs baseline: 1.0357x; 1.0066x over previous
#include <cuda_runtime.h>
#include <cuda_fp16.h>
#include <math.h>
#include <stdint.h>

// ---------------------------------------------------------------------------
// PredictorLG fused MLP:  LN -> (GEMM+GELU)x3 -> GEMM(->2) -> log_softmax
// R10: fp16 activation path + packed half2 GELU (tanh.approx.f16x2) to cut
// epilogue issue slots ~45%. Mainloop identical to R9 (full tensor rate).
// ---------------------------------------------------------------------------

#define ROWS_TILE   64
#define NTHREADS    256
#define LD          392           // padded activation row stride (halfs)
#define RTOT        262144
#define ROWS_PER_M  131072

#define S1 (384*384)
#define S2 (384*192)
#define S3 (192*96)
#define MOD_STRIDE (S1+S2+S3)
#define OFF_L2 (S1)
#define OFF_L3 (S1+S2)

__device__ __align__(16) __half g_packedW[2 * MOD_STRIDE];

// ---------------------------------------------------------------------------
// Weight repack: W[k][n] fp32 -> fp16 pair-kt B-fragment layout (16B/lane
// covers two consecutive kt):
//   dst = base + ((nt*KTP + ktp)*32 + lane)*8 + (kt&1)*4 + reg*2 + i
//   lane = (n%8)*4 + ((k%8)>>1);  reg = (k>>3)&1;  i = k&1
// ---------------------------------------------------------------------------
__global__ void pack_weights_kernel(const float* __restrict__ W1,
                                    const float* __restrict__ W2,
                                    const float* __restrict__ W3) {
    int idx = blockIdx.x * blockDim.x + threadIdx.x;
    const float* src;
    int K, N, r, m, layerOff;
    if (idx < 2 * S1) {
        m = idx / S1; r = idx % S1; K = 384; N = 384;
        src = W1 + m * S1; layerOff = 0;
    } else if (idx < 2 * (S1 + S2)) {
        int e = idx - 2 * S1;
        m = e / S2; r = e % S2; K = 384; N = 192;
        src = W2 + m * S2; layerOff = OFF_L2;
    } else if (idx < 2 * (S1 + S2 + S3)) {
        int e = idx - 2 * (S1 + S2);
        m = e / S3; r = e % S3; K = 192; N = 96;
        src = W3 + m * S3; layerOff = OFF_L3;
    } else {
        return;
    }
    int k = r / N, n = r % N;
    int kt  = k >> 4;
    int ktp = kt >> 1;
    int KTP = K >> 5;
    int nt  = n >> 3;
    int lane = (n & 7) * 4 + ((k & 7) >> 1);
    int reg  = (k >> 3) & 1;
    int i    = k & 1;
    int dst  = m * MOD_STRIDE + layerOff +
               ((nt * KTP + ktp) * 32 + lane) * 8 + (kt & 1) * 4 + reg * 2 + i;
    g_packedW[dst] = __float2half(src[k * N + n]);
}

// ---------------------------------------------------------------------------
// mma / ldmatrix / gelu helpers
// ---------------------------------------------------------------------------
__device__ __forceinline__ void mma16816(float c[4], const unsigned a[4],
                                         const unsigned b0, const unsigned b1) {
    asm volatile(
        "mma.sync.aligned.m16n8k16.row.col.f32.f16.f16.f32 "
        "{%0,%1,%2,%3}, {%4,%5,%6,%7}, {%8,%9}, {%0,%1,%2,%3};\n"
        : "+f"(c[0]), "+f"(c[1]), "+f"(c[2]), "+f"(c[3])
        : "r"(a[0]), "r"(a[1]), "r"(a[2]), "r"(a[3]), "r"(b0), "r"(b1));
}

__device__ __forceinline__ void ldmatrix_x4(unsigned r[4], uint32_t addr) {
    asm volatile(
        "ldmatrix.sync.aligned.m8n8.x4.shared.b16 {%0,%1,%2,%3}, [%4];\n"
        : "=r"(r[0]), "=r"(r[1]), "=r"(r[2]), "=r"(r[3])
        : "r"(addr));
}

// packed fp16 GELU (tanh approx, HW MUFU.TANH on f16x2)
__device__ __forceinline__ __half2 gelu_h2(__half2 v) {
    const __half2 c0 = __float2half2_rn(0.7978845608f);
    const __half2 c1 = __float2half2_rn(0.044715f);
    const __half2 hf = __float2half2_rn(0.5f);
    __half2 vv = __hmul2(v, v);
    __half2 u  = __hmul2(v, __hfma2(c1, vv, c0));
    unsigned ui = *(unsigned*)&u, ti;
    asm("tanh.approx.f16x2 %0, %1;" : "=r"(ti) : "r"(ui));
    __half2 t  = *(__half2*)&ti;
    __half2 hv = __hmul2(v, hf);
    return __hfma2(hv, t, hv);
}

// ---------------------------------------------------------------------------
// One GEMM layer: out = gelu(in[64,K] @ W[K,N] + bias), fp16 in/out, f32 acc.
// Warp grid 2(m) x 4(n). A fragments double-buffered; B pair-kt uint4,
// 2-slot prefetch. Epilogue: packed half2 bias+GELU+store.
// ---------------------------------------------------------------------------
template <int K, int N, int CHUNK>
__device__ __forceinline__ void gemm_layer(const __half* inBuf,
                                           __half* outBuf,
                                           const __half* __restrict__ Wp,
                                           const float* __restrict__ s_bias) {
    constexpr int NPASS = N / CHUNK;
    constexpr int CW  = CHUNK / 4;
    constexpr int NF  = CW / 8;
    constexpr int KT  = K / 16;
    constexpr int KTP = KT / 2;

    const int tid  = threadIdx.x;
    const int lane = tid & 31;
    const int wid  = tid >> 5;
    const int wm   = wid & 1;
    const int wn   = wid >> 1;

    uint32_t sA = (uint32_t)__cvta_generic_to_shared(inBuf);
    const int arow     = wm * 32 + (lane & 15);
    const int acol_off = (lane >> 4) * 8;
    const uint32_t aBase = sA + (uint32_t)((arow * LD + acol_off) * 2);

    const uint4* bb = (const uint4*)Wp;

#pragma unroll
    for (int p = 0; p < NPASS; ++p) {
        float acc[2][NF][4];
#pragma unroll
        for (int mi = 0; mi < 2; ++mi)
#pragma unroll
            for (int nf = 0; nf < NF; ++nf)
#pragma unroll
                for (int q = 0; q < 4; ++q) acc[mi][nf][q] = 0.f;

        const int colbase = p * CHUNK + wn * CW;
        const int ntbase  = colbase >> 3;
        const uint4* bwarp = bb + (size_t)ntbase * KTP * 32 + lane;

        // B: 2-slot circular pair prefetch
        uint4 bf[2][NF];
#pragma unroll
        for (int nf = 0; nf < NF; ++nf)
            bf[0][nf] = __ldg(bwarp + (size_t)nf * KTP * 32);

        // A: double-buffered fragments
        unsigned a[2][2][4];
        ldmatrix_x4(a[0][0], aBase);
        ldmatrix_x4(a[0][1], aBase + 16 * LD * 2);

#pragma unroll
        for (int kt = 0; kt < KT; ++kt) {
            const int ktp  = kt >> 1;
            const int acur = kt & 1;
            const int anxt = acur ^ 1;
            const int bcur = ktp & 1;

            if ((kt & 1) == 0 && ktp + 1 < KTP) {
#pragma unroll
                for (int nf = 0; nf < NF; ++nf)
                    bf[bcur ^ 1][nf] =
                        __ldg(bwarp + (size_t)nf * KTP * 32 + (ktp + 1) * 32);
            }
            if (kt + 1 < KT) {
                uint32_t addr1 = aBase + (uint32_t)((kt + 1) * 32);
                ldmatrix_x4(a[anxt][0], addr1);
                ldmatrix_x4(a[anxt][1], addr1 + 16 * LD * 2);
            }

#pragma unroll
            for (int nf = 0; nf < NF; ++nf) {
                const unsigned w0 = (kt & 1) ? bf[bcur][nf].z : bf[bcur][nf].x;
                const unsigned w1 = (kt & 1) ? bf[bcur][nf].w : bf[bcur][nf].y;
                mma16816(acc[0][nf], a[acur][0], w0, w1);
                mma16816(acc[1][nf], a[acur][1], w0, w1);
            }
        }

        // epilogue: bias + packed half2 gelu + store
        const int r0 = wm * 32 + (lane >> 2);
        const int cb = colbase + (lane & 3) * 2;
#pragma unroll
        for (int nf = 0; nf < NF; ++nf) {
            const int c = cb + nf * 8;
            const float bi0 = s_bias[c];
            const float bi1 = s_bias[c + 1];
#pragma unroll
            for (int mi = 0; mi < 2; ++mi) {
                const int row = r0 + mi * 16;
                __half2 p01 = __floats2half2_rn(acc[mi][nf][0] + bi0,
                                                acc[mi][nf][1] + bi1);
                __half2 p23 = __floats2half2_rn(acc[mi][nf][2] + bi0,
                                                acc[mi][nf][3] + bi1);
                *(__half2*)(outBuf + row * LD + c)       = gelu_h2(p01);
                *(__half2*)(outBuf + (row + 8) * LD + c) = gelu_h2(p23);
            }
        }
    }
}

// ---------------------------------------------------------------------------
// Fused kernel
// ---------------------------------------------------------------------------
__global__ void __launch_bounds__(NTHREADS, 2)
fused_mlp_kernel(const float* __restrict__ x,
                 const float* __restrict__ ln_g,
                 const float* __restrict__ ln_b,
                 const float* __restrict__ b1,
                 const float* __restrict__ b2,
                 const float* __restrict__ b3,
                 const float* __restrict__ W4,
                 const float* __restrict__ b4,
                 float* __restrict__ out) {
    extern __shared__ __align__(16) char smem_raw[];
    __half* bufA = (__half*)smem_raw;                               // [64][392]
    __half* bufB = bufA + ROWS_TILE * LD;                           // [64][392]
    float* s_bias = (float*)(bufB + ROWS_TILE * LD);                // [384]

    const int tid  = threadIdx.x;
    const int lane = tid & 31;
    const int wid  = tid >> 5;
    const long row0 = (long)blockIdx.x * ROWS_TILE;
    const int m = (int)(row0 / ROWS_PER_M);

    // ------------------- Stage 0: LayerNorm -> bufA (fp16) -----------------
    {
        float4 g4[3], bb4[3];
#pragma unroll
        for (int j = 0; j < 3; ++j) {
            g4[j]  = ((const float4*)(ln_g + m * 384))[j * 32 + lane];
            bb4[j] = ((const float4*)(ln_b + m * 384))[j * 32 + lane];
        }
#pragma unroll
        for (int r = wid; r < ROWS_TILE; r += 8) {
            const float4* xr = (const float4*)(x + (row0 + r) * 384);
            float4 v[3];
            float s = 0.f, q = 0.f;
#pragma unroll
            for (int j = 0; j < 3; ++j) {
                v[j] = xr[j * 32 + lane];
                s += v[j].x + v[j].y + v[j].z + v[j].w;
                q += v[j].x * v[j].x + v[j].y * v[j].y +
                     v[j].z * v[j].z + v[j].w * v[j].w;
            }
#pragma unroll
            for (int off = 16; off; off >>= 1) {
                s += __shfl_xor_sync(0xffffffffu, s, off);
                q += __shfl_xor_sync(0xffffffffu, q, off);
            }
            const float mu   = s * (1.0f / 384.0f);
            const float var  = q * (1.0f / 384.0f) - mu * mu;
            const float rinv = rsqrtf(var + 1e-5f);
#pragma unroll
            for (int j = 0; j < 3; ++j) {
                const int c = (j * 32 + lane) * 4;
                float y0 = (v[j].x - mu) * rinv * g4[j].x + bb4[j].x;
                float y1 = (v[j].y - mu) * rinv * g4[j].y + bb4[j].y;
                float y2 = (v[j].z - mu) * rinv * g4[j].z + bb4[j].z;
                float y3 = (v[j].w - mu) * rinv * g4[j].w + bb4[j].w;
                *(__half2*)(bufA + r * LD + c)     = __floats2half2_rn(y0, y1);
                *(__half2*)(bufA + r * LD + c + 2) = __floats2half2_rn(y2, y3);
            }
        }
    }

    const __half* WpBase = g_packedW + (size_t)m * MOD_STRIDE;

    // ------------------- Layer 1: 384 -> 384 (3 passes of 128) -------------
    __syncthreads();
    for (int i = tid; i < 384; i += NTHREADS) s_bias[i] = b1[m * 384 + i];
    __syncthreads();
    gemm_layer<384, 384, 128>(bufA, bufB, WpBase, s_bias);

    // ------------------- Layer 2: 384 -> 192 (2 passes of 96) --------------
    __syncthreads();
    if (tid < 192) s_bias[tid] = b2[m * 192 + tid];
    __syncthreads();
    gemm_layer<384, 192, 96>(bufB, bufA, WpBase + OFF_L2, s_bias);

    // ------------------- Layer 3: 192 -> 96 (1 pass of 96) -----------------
    __syncthreads();
    if (tid < 96) s_bias[tid] = b3[m * 96 + tid];
    __syncthreads();
    gemm_layer<192, 96, 96>(bufA, bufB, WpBase + OFF_L3, s_bias);

    // ------------------- Layer 4: 96 -> 2 + log_softmax --------------------
    __syncthreads();
    {
        const int r    = tid >> 2;
        const int part = tid & 3;
        const float* w4 = W4 + m * 96 * 2;
        const __half* hrow = bufB + r * LD;
        float z0 = 0.f, z1 = 0.f;
#pragma unroll
        for (int kk = 0; kk < 12; ++kk) {
            const int k = part * 24 + kk * 2;
            __half2 hv = *(const __half2*)(hrow + k);
            float a0 = __half2float(hv.x);
            float a1 = __half2float(hv.y);
            z0 += a0 * w4[k * 2]     + a1 * w4[(k + 1) * 2];
            z1 += a0 * w4[k * 2 + 1] + a1 * w4[(k + 1) * 2 + 1];
        }
        z0 += __shfl_xor_sync(0xffffffffu, z0, 1);
        z0 += __shfl_xor_sync(0xffffffffu, z0, 2);
        z1 += __shfl_xor_sync(0xffffffffu, z1, 1);
        z1 += __shfl_xor_sync(0xffffffffu, z1, 2);
        if (part == 0) {
            z0 += b4[m * 2 + 0];
            z1 += b4[m * 2 + 1];
            const float mx  = fmaxf(z0, z1);
            const float lse = mx + logf(expf(z0 - mx) + expf(z1 - mx));
            float* o = out + (row0 + r) * 2;
            o[0] = z0 - lse;
            o[1] = z1 - lse;
        }
    }
}

// ---------------------------------------------------------------------------
// Launch
// ---------------------------------------------------------------------------
extern "C" void kernel_launch(void* const* d_in, const int* in_sizes, int n_in,
                              void* d_out, int out_size) {
    const float* x    = (const float*)d_in[0];
    const float* ln_g = (const float*)d_in[1];
    const float* ln_b = (const float*)d_in[2];
    const float* W1   = (const float*)d_in[3];
    const float* b1   = (const float*)d_in[4];
    const float* W2   = (const float*)d_in[5];
    const float* b2   = (const float*)d_in[6];
    const float* W3   = (const float*)d_in[7];
    const float* b3   = (const float*)d_in[8];
    const float* W4   = (const float*)d_in[9];
    const float* b4   = (const float*)d_in[10];
    float* out        = (float*)d_out;

    const int packTotal = 2 * MOD_STRIDE;
    pack_weights_kernel<<<(packTotal + 255) / 256, 256>>>(W1, W2, W3);

    const int smem_bytes = 2 * ROWS_TILE * LD * (int)sizeof(__half)
                         + 384 * (int)sizeof(float);
    cudaFuncSetAttribute(fused_mlp_kernel,
                         cudaFuncAttributeMaxDynamicSharedMemorySize, smem_bytes);
    fused_mlp_kernel<<<RTOT / ROWS_TILE, NTHREADS, smem_bytes>>>(
        x, ln_g, ln_b, b1, b2, b3, W4, b4, out);
}

// round 11
// speedup vs baseline: 1.0876x; 1.0501x over previous
#include <cuda_runtime.h>
#include <cuda_fp16.h>
#include <math.h>
#include <stdint.h>

// ---------------------------------------------------------------------------
// PredictorLG fused MLP:  LN -> (GEMM+GELU)x3 -> GEMM(->2) -> log_softmax
// R11: break phase lockstep. The two wm-groups (4 warps each) are fully
// independent: named barriers (bar.sync 1+wm,128) instead of __syncthreads,
// group-local LN/L4, bias via __ldg (no smem staging). 4 independent
// pipelines per SM overlap MMA with LN/epilogue phases.
// ---------------------------------------------------------------------------

#define ROWS_TILE   64
#define NTHREADS    256
#define LD          392           // padded activation row stride (halfs)
#define RTOT        262144
#define ROWS_PER_M  131072

#define S1 (384*384)
#define S2 (384*192)
#define S3 (192*96)
#define MOD_STRIDE (S1+S2+S3)
#define OFF_L2 (S1)
#define OFF_L3 (S1+S2)

__device__ __align__(16) __half g_packedW[2 * MOD_STRIDE];

#define GROUP_BAR(wm) \
    asm volatile("bar.sync %0, 128;" :: "r"(1 + (wm)) : "memory")

// ---------------------------------------------------------------------------
// Weight repack: W[k][n] fp32 -> fp16 pair-kt B-fragment layout (16B/lane
// covers two consecutive kt):
//   dst = base + ((nt*KTP + ktp)*32 + lane)*8 + (kt&1)*4 + reg*2 + i
//   lane = (n%8)*4 + ((k%8)>>1);  reg = (k>>3)&1;  i = k&1
// ---------------------------------------------------------------------------
__global__ void pack_weights_kernel(const float* __restrict__ W1,
                                    const float* __restrict__ W2,
                                    const float* __restrict__ W3) {
    int idx = blockIdx.x * blockDim.x + threadIdx.x;
    const float* src;
    int K, N, r, m, layerOff;
    if (idx < 2 * S1) {
        m = idx / S1; r = idx % S1; K = 384; N = 384;
        src = W1 + m * S1; layerOff = 0;
    } else if (idx < 2 * (S1 + S2)) {
        int e = idx - 2 * S1;
        m = e / S2; r = e % S2; K = 384; N = 192;
        src = W2 + m * S2; layerOff = OFF_L2;
    } else if (idx < 2 * (S1 + S2 + S3)) {
        int e = idx - 2 * (S1 + S2);
        m = e / S3; r = e % S3; K = 192; N = 96;
        src = W3 + m * S3; layerOff = OFF_L3;
    } else {
        return;
    }
    int k = r / N, n = r % N;
    int kt  = k >> 4;
    int ktp = kt >> 1;
    int KTP = K >> 5;
    int nt  = n >> 3;
    int lane = (n & 7) * 4 + ((k & 7) >> 1);
    int reg  = (k >> 3) & 1;
    int i    = k & 1;
    int dst  = m * MOD_STRIDE + layerOff +
               ((nt * KTP + ktp) * 32 + lane) * 8 + (kt & 1) * 4 + reg * 2 + i;
    g_packedW[dst] = __float2half(src[k * N + n]);
}

// ---------------------------------------------------------------------------
// mma / ldmatrix / gelu helpers
// ---------------------------------------------------------------------------
__device__ __forceinline__ void mma16816(float c[4], const unsigned a[4],
                                         const unsigned b0, const unsigned b1) {
    asm volatile(
        "mma.sync.aligned.m16n8k16.row.col.f32.f16.f16.f32 "
        "{%0,%1,%2,%3}, {%4,%5,%6,%7}, {%8,%9}, {%0,%1,%2,%3};\n"
        : "+f"(c[0]), "+f"(c[1]), "+f"(c[2]), "+f"(c[3])
        : "r"(a[0]), "r"(a[1]), "r"(a[2]), "r"(a[3]), "r"(b0), "r"(b1));
}

__device__ __forceinline__ void ldmatrix_x4(unsigned r[4], uint32_t addr) {
    asm volatile(
        "ldmatrix.sync.aligned.m8n8.x4.shared.b16 {%0,%1,%2,%3}, [%4];\n"
        : "=r"(r[0]), "=r"(r[1]), "=r"(r[2]), "=r"(r[3])
        : "r"(addr));
}

// packed fp16 GELU (tanh approx, HW MUFU.TANH on f16x2)
__device__ __forceinline__ __half2 gelu_h2(__half2 v) {
    const __half2 c0 = __float2half2_rn(0.7978845608f);
    const __half2 c1 = __float2half2_rn(0.044715f);
    const __half2 hf = __float2half2_rn(0.5f);
    __half2 vv = __hmul2(v, v);
    __half2 u  = __hmul2(v, __hfma2(c1, vv, c0));
    unsigned ui = *(unsigned*)&u, ti;
    asm("tanh.approx.f16x2 %0, %1;" : "=r"(ti) : "r"(ui));
    __half2 t  = *(__half2*)&ti;
    __half2 hv = __hmul2(v, hf);
    return __hfma2(hv, t, hv);
}

// ---------------------------------------------------------------------------
// One GEMM layer (group-local, no barriers inside):
// out = gelu(in[64,K] @ W[K,N] + bias), fp16 in/out, f32 acc.
// Warp grid 2(m) x 4(n). A double-buffered; B pair-kt uint4, 2-slot prefetch.
// Bias loaded to regs via __ldg at pass start (overlaps mainloop).
// ---------------------------------------------------------------------------
template <int K, int N, int CHUNK>
__device__ __forceinline__ void gemm_layer(const __half* inBuf,
                                           __half* outBuf,
                                           const __half* __restrict__ Wp,
                                           const float* __restrict__ bias) {
    constexpr int NPASS = N / CHUNK;
    constexpr int CW  = CHUNK / 4;
    constexpr int NF  = CW / 8;
    constexpr int KT  = K / 16;
    constexpr int KTP = KT / 2;

    const int tid  = threadIdx.x;
    const int lane = tid & 31;
    const int wid  = tid >> 5;
    const int wm   = wid & 1;
    const int wn   = wid >> 1;

    uint32_t sA = (uint32_t)__cvta_generic_to_shared(inBuf);
    const int arow     = wm * 32 + (lane & 15);
    const int acol_off = (lane >> 4) * 8;
    const uint32_t aBase = sA + (uint32_t)((arow * LD + acol_off) * 2);

    const uint4* bb = (const uint4*)Wp;

#pragma unroll
    for (int p = 0; p < NPASS; ++p) {
        float acc[2][NF][4];
#pragma unroll
        for (int mi = 0; mi < 2; ++mi)
#pragma unroll
            for (int nf = 0; nf < NF; ++nf)
#pragma unroll
                for (int q = 0; q < 4; ++q) acc[mi][nf][q] = 0.f;

        const int colbase = p * CHUNK + wn * CW;
        const int ntbase  = colbase >> 3;
        const uint4* bwarp = bb + (size_t)ntbase * KTP * 32 + lane;
        const int cb = colbase + (lane & 3) * 2;

        // bias into regs (overlaps mainloop latency)
        float bi[NF][2];
#pragma unroll
        for (int nf = 0; nf < NF; ++nf) {
            bi[nf][0] = __ldg(bias + cb + nf * 8);
            bi[nf][1] = __ldg(bias + cb + nf * 8 + 1);
        }

        // B: 2-slot circular pair prefetch
        uint4 bf[2][NF];
#pragma unroll
        for (int nf = 0; nf < NF; ++nf)
            bf[0][nf] = __ldg(bwarp + (size_t)nf * KTP * 32);

        // A: double-buffered fragments
        unsigned a[2][2][4];
        ldmatrix_x4(a[0][0], aBase);
        ldmatrix_x4(a[0][1], aBase + 16 * LD * 2);

#pragma unroll
        for (int kt = 0; kt < KT; ++kt) {
            const int ktp  = kt >> 1;
            const int acur = kt & 1;
            const int anxt = acur ^ 1;
            const int bcur = ktp & 1;

            if ((kt & 1) == 0 && ktp + 1 < KTP) {
#pragma unroll
                for (int nf = 0; nf < NF; ++nf)
                    bf[bcur ^ 1][nf] =
                        __ldg(bwarp + (size_t)nf * KTP * 32 + (ktp + 1) * 32);
            }
            if (kt + 1 < KT) {
                uint32_t addr1 = aBase + (uint32_t)((kt + 1) * 32);
                ldmatrix_x4(a[anxt][0], addr1);
                ldmatrix_x4(a[anxt][1], addr1 + 16 * LD * 2);
            }

#pragma unroll
            for (int nf = 0; nf < NF; ++nf) {
                const unsigned w0 = (kt & 1) ? bf[bcur][nf].z : bf[bcur][nf].x;
                const unsigned w1 = (kt & 1) ? bf[bcur][nf].w : bf[bcur][nf].y;
                mma16816(acc[0][nf], a[acur][0], w0, w1);
                mma16816(acc[1][nf], a[acur][1], w0, w1);
            }
        }

        // epilogue: bias + packed half2 gelu + store
        const int r0 = wm * 32 + (lane >> 2);
#pragma unroll
        for (int nf = 0; nf < NF; ++nf) {
            const int c = cb + nf * 8;
#pragma unroll
            for (int mi = 0; mi < 2; ++mi) {
                const int row = r0 + mi * 16;
                __half2 p01 = __floats2half2_rn(acc[mi][nf][0] + bi[nf][0],
                                                acc[mi][nf][1] + bi[nf][1]);
                __half2 p23 = __floats2half2_rn(acc[mi][nf][2] + bi[nf][0],
                                                acc[mi][nf][3] + bi[nf][1]);
                *(__half2*)(outBuf + row * LD + c)       = gelu_h2(p01);
                *(__half2*)(outBuf + (row + 8) * LD + c) = gelu_h2(p23);
            }
        }
    }
}

// ---------------------------------------------------------------------------
// Fused kernel — two fully independent 128-thread pipelines per CTA.
// ---------------------------------------------------------------------------
__global__ void __launch_bounds__(NTHREADS, 2)
fused_mlp_kernel(const float* __restrict__ x,
                 const float* __restrict__ ln_g,
                 const float* __restrict__ ln_b,
                 const float* __restrict__ b1,
                 const float* __restrict__ b2,
                 const float* __restrict__ b3,
                 const float* __restrict__ W4,
                 const float* __restrict__ b4,
                 float* __restrict__ out) {
    extern __shared__ __align__(16) char smem_raw[];
    __half* bufA = (__half*)smem_raw;                               // [64][392]
    __half* bufB = bufA + ROWS_TILE * LD;                           // [64][392]

    const int tid  = threadIdx.x;
    const int lane = tid & 31;
    const int wid  = tid >> 5;
    const int wm   = wid & 1;
    const int wn   = wid >> 1;
    const long row0 = (long)blockIdx.x * ROWS_TILE;
    const int m = (int)(row0 / ROWS_PER_M);

    // ------------------- Stage 0: LayerNorm -> bufA (fp16), group-local ----
    {
        float4 g4[3], bb4[3];
#pragma unroll
        for (int j = 0; j < 3; ++j) {
            g4[j]  = ((const float4*)(ln_g + m * 384))[j * 32 + lane];
            bb4[j] = ((const float4*)(ln_b + m * 384))[j * 32 + lane];
        }
        // group wm handles rows [wm*32, wm*32+32); warp wn takes 8 of them
#pragma unroll
        for (int t = 0; t < 8; ++t) {
            const int r = wm * 32 + wn * 8 + t;
            const float4* xr = (const float4*)(x + (row0 + r) * 384);
            float4 v[3];
            float s = 0.f, q = 0.f;
#pragma unroll
            for (int j = 0; j < 3; ++j) {
                v[j] = xr[j * 32 + lane];
                s += v[j].x + v[j].y + v[j].z + v[j].w;
                q += v[j].x * v[j].x + v[j].y * v[j].y +
                     v[j].z * v[j].z + v[j].w * v[j].w;
            }
#pragma unroll
            for (int off = 16; off; off >>= 1) {
                s += __shfl_xor_sync(0xffffffffu, s, off);
                q += __shfl_xor_sync(0xffffffffu, q, off);
            }
            const float mu   = s * (1.0f / 384.0f);
            const float var  = q * (1.0f / 384.0f) - mu * mu;
            const float rinv = rsqrtf(var + 1e-5f);
#pragma unroll
            for (int j = 0; j < 3; ++j) {
                const int c = (j * 32 + lane) * 4;
                float y0 = (v[j].x - mu) * rinv * g4[j].x + bb4[j].x;
                float y1 = (v[j].y - mu) * rinv * g4[j].y + bb4[j].y;
                float y2 = (v[j].z - mu) * rinv * g4[j].z + bb4[j].z;
                float y3 = (v[j].w - mu) * rinv * g4[j].w + bb4[j].w;
                *(__half2*)(bufA + r * LD + c)     = __floats2half2_rn(y0, y1);
                *(__half2*)(bufA + r * LD + c + 2) = __floats2half2_rn(y2, y3);
            }
        }
    }

    const __half* WpBase = g_packedW + (size_t)m * MOD_STRIDE;

    // ------------------- Layer 1: 384 -> 384 (3 passes of 128) -------------
    GROUP_BAR(wm);
    gemm_layer<384, 384, 128>(bufA, bufB, WpBase, b1 + m * 384);

    // ------------------- Layer 2: 384 -> 192 (2 passes of 96) --------------
    GROUP_BAR(wm);
    gemm_layer<384, 192, 96>(bufB, bufA, WpBase + OFF_L2, b2 + m * 192);

    // ------------------- Layer 3: 192 -> 96 (1 pass of 96) -----------------
    GROUP_BAR(wm);
    gemm_layer<192, 96, 96>(bufA, bufB, WpBase + OFF_L3, b3 + m * 96);

    // ------------------- Layer 4: 96 -> 2 + log_softmax (group-local) ------
    GROUP_BAR(wm);
    {
        const int glt  = wn * 32 + lane;          // 0..127 within group
        const int r    = wm * 32 + (glt >> 2);    // 32 rows per group
        const int part = glt & 3;
        const float* w4 = W4 + m * 192;
        const __half* hrow = bufB + r * LD;
        float z0 = 0.f, z1 = 0.f;
#pragma unroll
        for (int kk = 0; kk < 12; ++kk) {
            const int k = part * 24 + kk * 2;
            __half2 hv = *(const __half2*)(hrow + k);
            float a0 = __half2float(hv.x);
            float a1 = __half2float(hv.y);
            z0 += a0 * __ldg(w4 + k * 2)       + a1 * __ldg(w4 + (k + 1) * 2);
            z1 += a0 * __ldg(w4 + k * 2 + 1)   + a1 * __ldg(w4 + (k + 1) * 2 + 1);
        }
        z0 += __shfl_xor_sync(0xffffffffu, z0, 1);
        z0 += __shfl_xor_sync(0xffffffffu, z0, 2);
        z1 += __shfl_xor_sync(0xffffffffu, z1, 1);
        z1 += __shfl_xor_sync(0xffffffffu, z1, 2);
        if (part == 0) {
            z0 += __ldg(b4 + m * 2 + 0);
            z1 += __ldg(b4 + m * 2 + 1);
            const float mx  = fmaxf(z0, z1);
            const float lse = mx + logf(expf(z0 - mx) + expf(z1 - mx));
            float* o = out + (row0 + r) * 2;
            o[0] = z0 - lse;
            o[1] = z1 - lse;
        }
    }
}

// ---------------------------------------------------------------------------
// Launch
// ---------------------------------------------------------------------------
extern "C" void kernel_launch(void* const* d_in, const int* in_sizes, int n_in,
                              void* d_out, int out_size) {
    const float* x    = (const float*)d_in[0];
    const float* ln_g = (const float*)d_in[1];
    const float* ln_b = (const float*)d_in[2];
    const float* W1   = (const float*)d_in[3];
    const float* b1   = (const float*)d_in[4];
    const float* W2   = (const float*)d_in[5];
    const float* b2   = (const float*)d_in[6];
    const float* W3   = (const float*)d_in[7];
    const float* b3   = (const float*)d_in[8];
    const float* W4   = (const float*)d_in[9];
    const float* b4   = (const float*)d_in[10];
    float* out        = (float*)d_out;

    const int packTotal = 2 * MOD_STRIDE;
    pack_weights_kernel<<<(packTotal + 255) / 256, 256>>>(W1, W2, W3);

    const int smem_bytes = 2 * ROWS_TILE * LD * (int)sizeof(__half);
    cudaFuncSetAttribute(fused_mlp_kernel,
                         cudaFuncAttributeMaxDynamicSharedMemorySize, smem_bytes);
    fused_mlp_kernel<<<RTOT / ROWS_TILE, NTHREADS, smem_bytes>>>(
        x, ln_g, ln_b, b1, b2, b3, W4, b4, out);
}